// round 17
// baseline (speedup 1.0000x reference)
#include <cuda_runtime.h>
#include <cstdint>
#include <math.h>

// Problem constants
#define LL 512
#define DD 128
#define HB 128          // H*B
#define MM 8192         // B*L
#define HD 1024
#define INV_SQRT_D 0.08838834764831843f

// ---------------------------------------------------------------------------
// Scratch (device globals; allocation is forbidden)
// All GEMM operands except S live as pre-split bf16 hi/lo planes.
// ---------------------------------------------------------------------------
__device__ __align__(128) uint16_t g_xh[MM * DD],  g_xl[MM * DD];
__device__ __align__(128) uint16_t g_Wh[3 * HD * DD], g_Wl[3 * HD * DD];
__device__ __align__(128) uint16_t g_Woh[DD * HD], g_Wol[DD * HD];
__device__ __align__(128) uint16_t g_Qh[HB * LL * DD], g_Ql[HB * LL * DD];
__device__ __align__(128) uint16_t g_Kh[HB * LL * DD], g_Kl[HB * LL * DD];
__device__ __align__(128) uint16_t g_Vh[HB * DD * LL], g_Vl[HB * DD * LL];   // Vt: [n][d][l]
__device__ __align__(128) uint16_t g_Ah[MM * HD],  g_Al[MM * HD];            // ATT flat
__device__ __align__(128) float g_S[HB * LL * LL];     // raw masked+scaled scores
// Query-axis softmax stats
__device__ __align__(128) float g_pmax[4 * HB * LL];
__device__ __align__(128) float g_psum[4 * HB * LL];
__device__ __align__(128) float g_M[HB * LL];
__device__ __align__(128) float g_inv[HB * LL];

// ---------------------------------------------------------------------------
// Tiling: block 128x128, warps 4(m) x 2(n), warp tile 32x64, K chunk 32.
// fp32 tile pad 40 floats (k_av A); bf16 tile pad 40 halfs (20 words: loads
// at word 20g+t = 4*(5g mod 8)+t cover all 32 banks — conflict-free LDS.32).
// ---------------------------------------------------------------------------
#define KC 32
#define RP_F 40
#define TB_F (128 * RP_F * 4)          // 20480
#define RP_H 40
#define TB_H (128 * RP_H * 2)          // 10240
#define SMEM_BYTES 81920               // PRE: 8*TB_H; AV: 2*TB_F + 4*TB_H

__device__ __forceinline__ uint32_t smem_u32(const void* p) {
    uint32_t a;
    asm("{ .reg .u64 t; cvta.to.shared.u64 t, %1; cvt.u32.u64 %0, t; }" : "=r"(a) : "l"(p));
    return a;
}
__device__ __forceinline__ void cp16(uint32_t saddr, const void* g) {
    asm volatile("cp.async.cg.shared.global [%0], [%1], 16;" :: "r"(saddr), "l"(g));
}
#define CP_COMMIT() asm volatile("cp.async.commit_group;" ::: "memory")
#define CP_WAIT(N)  asm volatile("cp.async.wait_group %0;" :: "n"(N) : "memory")

// Split two fp32 (adjacent k) into packed bf16x2 hi (truncation) and lo (residual).
__device__ __forceinline__ void split_bf16(float v0, float v1, uint32_t& hi, uint32_t& lo) {
    uint32_t u0 = __float_as_uint(v0);
    uint32_t u1 = __float_as_uint(v1);
    asm("prmt.b32 %0, %1, %2, 0x7632;" : "=r"(hi) : "r"(u0), "r"(u1));
    float r0 = v0 - __uint_as_float(u0 & 0xffff0000u);
    float r1 = v1 - __uint_as_float(u1 & 0xffff0000u);
    asm("cvt.rn.bf16x2.f32 %0, %1, %2;" : "=r"(lo) : "f"(r1), "f"(r0));
}

__device__ __forceinline__ void mma16(float acc[4],
                                      uint32_t a0, uint32_t a1, uint32_t a2, uint32_t a3,
                                      uint32_t b0, uint32_t b1) {
    asm volatile(
        "mma.sync.aligned.m16n8k16.row.col.f32.bf16.bf16.f32 "
        "{%0,%1,%2,%3}, {%4,%5,%6,%7}, {%8,%9}, {%0,%1,%2,%3};"
        : "+f"(acc[0]), "+f"(acc[1]), "+f"(acc[2]), "+f"(acc[3])
        : "r"(a0), "r"(a1), "r"(a2), "r"(a3), "r"(b0), "r"(b1));
}

// fp32 128x32 tile (row stride ld floats) -> smem, pad RP_F.
__device__ __forceinline__ void load_async_f(uint32_t sbase, const float* __restrict__ src,
                                             int ld, int tid) {
#pragma unroll
    for (int i = 0; i < 4; ++i) {
        int idx = tid + i * 256;
        int row = idx >> 3;
        int c4 = idx & 7;
        cp16(sbase + (row * RP_F + c4 * 4) * 4, src + row * ld + c4 * 4);
    }
}
// bf16 128x32 tile (row stride ld halfs) -> smem, pad RP_H.
__device__ __forceinline__ void load_async_h(uint32_t sbase, const uint16_t* __restrict__ src,
                                             int ld, int tid) {
#pragma unroll
    for (int i = 0; i < 2; ++i) {
        int idx = tid + i * 256;
        int row = idx >> 2;
        int c = idx & 3;
        cp16(sbase + row * (RP_H * 2) + c * 16, src + row * ld + c * 8);
    }
}

// ---------------------------------------------------------------------------
// PRE chunk: both operands pre-split bf16 planes. Pure LDS.32 + HMMA.
// ---------------------------------------------------------------------------
__device__ __forceinline__ void chunk_pre(const uint16_t (*Ah)[RP_H], const uint16_t (*Al)[RP_H],
                                          const uint16_t (*Bh)[RP_H], const uint16_t (*Bl)[RP_H],
                                          int wm, int wn, int g, int t, float acc[2][8][4]) {
#pragma unroll
    for (int ks = 0; ks < 2; ++ks) {
        int k0 = ks * 16 + 2 * t;
        uint32_t ah[2][4], al[2][4];
#pragma unroll
        for (int mt = 0; mt < 2; ++mt) {
            int r = wm * 32 + mt * 16;
            ah[mt][0] = *(const uint32_t*)&Ah[r + g][k0];
            ah[mt][1] = *(const uint32_t*)&Ah[r + g + 8][k0];
            ah[mt][2] = *(const uint32_t*)&Ah[r + g][k0 + 8];
            ah[mt][3] = *(const uint32_t*)&Ah[r + g + 8][k0 + 8];
            al[mt][0] = *(const uint32_t*)&Al[r + g][k0];
            al[mt][1] = *(const uint32_t*)&Al[r + g + 8][k0];
            al[mt][2] = *(const uint32_t*)&Al[r + g][k0 + 8];
            al[mt][3] = *(const uint32_t*)&Al[r + g + 8][k0 + 8];
        }
#pragma unroll
        for (int nt = 0; nt < 8; ++nt) {
            int c = wn * 64 + nt * 8;
            uint32_t bh0 = *(const uint32_t*)&Bh[c + g][k0];
            uint32_t bh1 = *(const uint32_t*)&Bh[c + g][k0 + 8];
            uint32_t bl0 = *(const uint32_t*)&Bl[c + g][k0];
            uint32_t bl1 = *(const uint32_t*)&Bl[c + g][k0 + 8];
            mma16(acc[0][nt], ah[0][0], ah[0][1], ah[0][2], ah[0][3], bh0, bh1);
            mma16(acc[1][nt], ah[1][0], ah[1][1], ah[1][2], ah[1][3], bh0, bh1);
            mma16(acc[0][nt], ah[0][0], ah[0][1], ah[0][2], ah[0][3], bl0, bl1);
            mma16(acc[1][nt], ah[1][0], ah[1][1], ah[1][2], ah[1][3], bl0, bl1);
            mma16(acc[0][nt], al[0][0], al[0][1], al[0][2], al[0][3], bh0, bh1);
            mma16(acc[1][nt], al[1][0], al[1][1], al[1][2], al[1][3], bh0, bh1);
        }
    }
}

// AV chunk: A = fp32 S with fused exp+split; B pre-split planes.
__device__ __forceinline__ void chunk_av(const float (*As)[RP_F],
                                         const uint16_t (*Bh)[RP_H], const uint16_t (*Bl)[RP_H],
                                         int wm, int wn, int g, int t,
                                         const float* __restrict__ Mrow,
                                         const float* __restrict__ Irow,
                                         float acc[2][8][4]) {
#pragma unroll
    for (int ks = 0; ks < 2; ++ks) {
        int k0 = ks * 16 + 2 * t;
        int k1 = k0 + 8;
        float2 m0 = *(const float2*)&Mrow[k0];
        float2 i0 = *(const float2*)&Irow[k0];
        float2 m1 = *(const float2*)&Mrow[k1];
        float2 i1 = *(const float2*)&Irow[k1];
        uint32_t ah[2][4], al[2][4];
#pragma unroll
        for (int mt = 0; mt < 2; ++mt) {
            int r = wm * 32 + mt * 16;
            float2 v00 = *(const float2*)&As[r + g][k0];
            float2 v10 = *(const float2*)&As[r + g + 8][k0];
            float2 v01 = *(const float2*)&As[r + g][k1];
            float2 v11 = *(const float2*)&As[r + g + 8][k1];
            v00.x = __expf(v00.x - m0.x) * i0.x; v00.y = __expf(v00.y - m0.y) * i0.y;
            v10.x = __expf(v10.x - m0.x) * i0.x; v10.y = __expf(v10.y - m0.y) * i0.y;
            v01.x = __expf(v01.x - m1.x) * i1.x; v01.y = __expf(v01.y - m1.y) * i1.y;
            v11.x = __expf(v11.x - m1.x) * i1.x; v11.y = __expf(v11.y - m1.y) * i1.y;
            split_bf16(v00.x, v00.y, ah[mt][0], al[mt][0]);
            split_bf16(v10.x, v10.y, ah[mt][1], al[mt][1]);
            split_bf16(v01.x, v01.y, ah[mt][2], al[mt][2]);
            split_bf16(v11.x, v11.y, ah[mt][3], al[mt][3]);
        }
#pragma unroll
        for (int nt = 0; nt < 8; ++nt) {
            int c = wn * 64 + nt * 8;
            uint32_t bh0 = *(const uint32_t*)&Bh[c + g][k0];
            uint32_t bh1 = *(const uint32_t*)&Bh[c + g][k0 + 8];
            uint32_t bl0 = *(const uint32_t*)&Bl[c + g][k0];
            uint32_t bl1 = *(const uint32_t*)&Bl[c + g][k0 + 8];
            mma16(acc[0][nt], ah[0][0], ah[0][1], ah[0][2], ah[0][3], bh0, bh1);
            mma16(acc[1][nt], ah[1][0], ah[1][1], ah[1][2], ah[1][3], bh0, bh1);
            mma16(acc[0][nt], ah[0][0], ah[0][1], ah[0][2], ah[0][3], bl0, bl1);
            mma16(acc[1][nt], ah[1][0], ah[1][1], ah[1][2], ah[1][3], bl0, bl1);
            mma16(acc[0][nt], al[0][0], al[0][1], al[0][2], al[0][3], bh0, bh1);
            mma16(acc[1][nt], al[1][0], al[1][1], al[1][2], al[1][3], bh0, bh1);
        }
    }
}

// PRE main loop. smem layout: [Ah0,Ah1, Al0,Al1, Bh0,Bh1, Bl0,Bl1] x TB_H.
__device__ __forceinline__ void gemm_pre(char* sm, uint32_t smb,
                                         const uint16_t* __restrict__ Ahg, const uint16_t* __restrict__ Alg,
                                         const uint16_t* __restrict__ Bhg, const uint16_t* __restrict__ Blg,
                                         int lda, int ldb, int nc,
                                         int tid, int wm, int wn, int g, int t,
                                         float acc[2][8][4]) {
    load_async_h(smb,            Ahg, lda, tid);
    load_async_h(smb + 2 * TB_H, Alg, lda, tid);
    load_async_h(smb + 4 * TB_H, Bhg, ldb, tid);
    load_async_h(smb + 6 * TB_H, Blg, ldb, tid);
    CP_COMMIT();
#pragma unroll 1
    for (int c = 0; c < nc; ++c) {
        if (c + 1 < nc) {
            int nb = (c + 1) & 1;
            load_async_h(smb + nb * TB_H,           Ahg + (c + 1) * KC, lda, tid);
            load_async_h(smb + (2 + nb) * TB_H,     Alg + (c + 1) * KC, lda, tid);
            load_async_h(smb + (4 + nb) * TB_H,     Bhg + (c + 1) * KC, ldb, tid);
            load_async_h(smb + (6 + nb) * TB_H,     Blg + (c + 1) * KC, ldb, tid);
            CP_COMMIT();
            CP_WAIT(1);
        } else {
            CP_WAIT(0);
        }
        __syncthreads();
        int cb = c & 1;
        chunk_pre((const uint16_t(*)[RP_H])(sm + cb * TB_H),
                  (const uint16_t(*)[RP_H])(sm + (2 + cb) * TB_H),
                  (const uint16_t(*)[RP_H])(sm + (4 + cb) * TB_H),
                  (const uint16_t(*)[RP_H])(sm + (6 + cb) * TB_H),
                  wm, wn, g, t, acc);
        __syncthreads();
    }
}

// AV main loop. smem layout: [S0,S1] x TB_F, then [Bh0,Bh1, Bl0,Bl1] x TB_H.
__device__ __forceinline__ void gemm_av(char* sm, uint32_t smb,
                                        const float* __restrict__ Ag,
                                        const uint16_t* __restrict__ Bhg, const uint16_t* __restrict__ Blg,
                                        int lda, int ldb, int nc,
                                        int tid, int wm, int wn, int g, int t,
                                        const float* __restrict__ Mb, const float* __restrict__ Ib,
                                        float acc[2][8][4]) {
    const uint32_t bh_base = smb + 2 * TB_F;
    const uint32_t bl_base = smb + 2 * TB_F + 2 * TB_H;
    load_async_f(smb,     Ag,  lda, tid);
    load_async_h(bh_base, Bhg, ldb, tid);
    load_async_h(bl_base, Blg, ldb, tid);
    CP_COMMIT();
#pragma unroll 1
    for (int c = 0; c < nc; ++c) {
        if (c + 1 < nc) {
            int nb = (c + 1) & 1;
            load_async_f(smb + nb * TB_F,     Ag  + (c + 1) * KC, lda, tid);
            load_async_h(bh_base + nb * TB_H, Bhg + (c + 1) * KC, ldb, tid);
            load_async_h(bl_base + nb * TB_H, Blg + (c + 1) * KC, ldb, tid);
            CP_COMMIT();
            CP_WAIT(1);
        } else {
            CP_WAIT(0);
        }
        __syncthreads();
        int cb = c & 1;
        chunk_av((const float(*)[RP_F])(sm + cb * TB_F),
                 (const uint16_t(*)[RP_H])(sm + 2 * TB_F + cb * TB_H),
                 (const uint16_t(*)[RP_H])(sm + 2 * TB_F + 2 * TB_H + cb * TB_H),
                 wm, wn, g, t, Mb + c * KC, Ib + c * KC, acc);
        __syncthreads();
    }
}

// ---------------------------------------------------------------------------
// K0: convert fp32 -> bf16 hi/lo planes. Grid-stride over pairs.
// ---------------------------------------------------------------------------
__global__ __launch_bounds__(256) void k_convert(const float* __restrict__ src,
                                                 uint16_t* __restrict__ dh,
                                                 uint16_t* __restrict__ dl, int npairs) {
    int i = blockIdx.x * 256 + threadIdx.x;
    if (i < npairs) {
        float2 v = *(const float2*)(src + 2 * i);
        uint32_t h, l;
        split_bf16(v.x, v.y, h, l);
        *(uint32_t*)&dh[2 * i] = h;
        *(uint32_t*)&dl[2 * i] = l;
    }
}

// ---------------------------------------------------------------------------
// K1: QKV projection from pre-split x/W planes. grid (8, 64, 3), block 256.
// Epilogue writes Q/K (hi/lo planes) or Vt (scalar-scattered planes).
// ---------------------------------------------------------------------------
__global__ __launch_bounds__(256) void k_qkv(
    const float* __restrict__ bq, const float* __restrict__ bk, const float* __restrict__ bv) {
    extern __shared__ char sm[];
    uint32_t smb = smem_u32(sm);
    int tid = threadIdx.x, wid = tid >> 5, lane = tid & 31;
    int wm = wid & 3, wn = wid >> 2, g = lane >> 2, t = lane & 3;
    int sel = blockIdx.z;
    int e0 = blockIdx.x * 128;
    int m0 = blockIdx.y * 128;
    const float* bias = (sel == 0) ? bq : (sel == 1) ? bk : bv;

    float acc[2][8][4] = {};
    gemm_pre(sm, smb, g_xh + m0 * DD, g_xl + m0 * DD,
             g_Wh + sel * (HD * DD) + e0 * DD, g_Wl + sel * (HD * DD) + e0 * DD,
             DD, DD, 4, tid, wm, wn, g, t, acc);

    int h = e0 >> 7;
#pragma unroll
    for (int mt = 0; mt < 2; ++mt) {
#pragma unroll
        for (int nt = 0; nt < 8; ++nt) {
            int col = wn * 64 + nt * 8 + t * 2;
            float bi0 = bias[e0 + col], bi1 = bias[e0 + col + 1];
#pragma unroll
            for (int half = 0; half < 2; ++half) {
                int row = wm * 32 + mt * 16 + g + half * 8;
                int m = m0 + row;
                int b = m >> 9, l = m & 511;
                int n = (h << 4) + b;
                float v0 = acc[mt][nt][half * 2] + bi0;
                float v1 = acc[mt][nt][half * 2 + 1] + bi1;
                uint32_t hh, ll;
                split_bf16(v0, v1, hh, ll);
                if (sel < 2) {
                    int idx = (n * LL + l) * DD + col;
                    if (sel == 0) { *(uint32_t*)&g_Qh[idx] = hh; *(uint32_t*)&g_Ql[idx] = ll; }
                    else          { *(uint32_t*)&g_Kh[idx] = hh; *(uint32_t*)&g_Kl[idx] = ll; }
                } else {
                    int base = n * (DD * LL) + l;
                    g_Vh[base + col * LL]       = (uint16_t)hh;
                    g_Vh[base + (col + 1) * LL] = (uint16_t)(hh >> 16);
                    g_Vl[base + col * LL]       = (uint16_t)ll;
                    g_Vl[base + (col + 1) * LL] = (uint16_t)(ll >> 16);
                }
            }
        }
    }
}

// ---------------------------------------------------------------------------
// K2: scores + per-block column softmax partials. grid (4, 4, 128), block 256.
// ---------------------------------------------------------------------------
__global__ __launch_bounds__(256) void k_scores(const int* __restrict__ mask) {
    extern __shared__ char sm[];
    uint32_t smb = smem_u32(sm);
    int tid = threadIdx.x, wid = tid >> 5, lane = tid & 31;
    int wm = wid & 3, wn = wid >> 2, g = lane >> 2, t = lane & 3;
    int n = blockIdx.z;
    int kc0 = blockIdx.x * 128;
    int q0 = blockIdx.y * 128;

    float acc[2][8][4] = {};
    gemm_pre(sm, smb, g_Qh + (n * LL + q0) * DD, g_Ql + (n * LL + q0) * DD,
             g_Kh + (n * LL + kc0) * DD, g_Kl + (n * LL + kc0) * DD,
             DD, DD, 4, tid, wm, wn, g, t, acc);

    // Mask + scale into acc; store raw S.
    const int* mbase = mask + (n & 15) * (LL * LL);
    float* sbase = g_S + n * (LL * LL);
#pragma unroll
    for (int mt = 0; mt < 2; ++mt) {
#pragma unroll
        for (int nt = 0; nt < 8; ++nt) {
            int col = kc0 + wn * 64 + nt * 8 + t * 2;
#pragma unroll
            for (int half = 0; half < 2; ++half) {
                int q = q0 + wm * 32 + mt * 16 + g + half * 8;
                int2 mk = *(const int2*)(mbase + q * LL + col);
                float v0 = (mk.x ? -1e9f : acc[mt][nt][half * 2]) * INV_SQRT_D;
                float v1 = (mk.y ? -1e9f : acc[mt][nt][half * 2 + 1]) * INV_SQRT_D;
                *(float2*)(sbase + q * LL + col) = make_float2(v0, v1);
                acc[mt][nt][half * 2] = v0;
                acc[mt][nt][half * 2 + 1] = v1;
            }
        }
    }

    // Column stats over this block's 128 q rows (softmax is over the q axis).
    float* smax = (float*)sm;
    float* ssum = ((float*)sm) + 512;
    __syncthreads();

#pragma unroll
    for (int nt = 0; nt < 8; ++nt)
#pragma unroll
        for (int e = 0; e < 2; ++e) {
            float m = fmaxf(fmaxf(acc[0][nt][e], acc[0][nt][2 + e]),
                            fmaxf(acc[1][nt][e], acc[1][nt][2 + e]));
            m = fmaxf(m, __shfl_xor_sync(0xffffffffu, m, 16));
            m = fmaxf(m, __shfl_xor_sync(0xffffffffu, m, 8));
            m = fmaxf(m, __shfl_xor_sync(0xffffffffu, m, 4));
            if (g == 0) smax[wm * 128 + wn * 64 + nt * 8 + t * 2 + e] = m;
        }
    __syncthreads();
    float Mcol[8][2];
#pragma unroll
    for (int nt = 0; nt < 8; ++nt)
#pragma unroll
        for (int e = 0; e < 2; ++e) {
            int col = wn * 64 + nt * 8 + t * 2 + e;
            Mcol[nt][e] = fmaxf(fmaxf(smax[col], smax[128 + col]),
                                fmaxf(smax[256 + col], smax[384 + col]));
        }
#pragma unroll
    for (int nt = 0; nt < 8; ++nt)
#pragma unroll
        for (int e = 0; e < 2; ++e) {
            float Mv = Mcol[nt][e];
            float z = __expf(acc[0][nt][e] - Mv) + __expf(acc[0][nt][2 + e] - Mv)
                    + __expf(acc[1][nt][e] - Mv) + __expf(acc[1][nt][2 + e] - Mv);
            z += __shfl_xor_sync(0xffffffffu, z, 16);
            z += __shfl_xor_sync(0xffffffffu, z, 8);
            z += __shfl_xor_sync(0xffffffffu, z, 4);
            if (g == 0) ssum[wm * 128 + wn * 64 + nt * 8 + t * 2 + e] = z;
        }
    __syncthreads();
    if (wm == 0 && g == 0) {
#pragma unroll
        for (int nt = 0; nt < 8; ++nt)
#pragma unroll
            for (int e = 0; e < 2; ++e) {
                int col = wn * 64 + nt * 8 + t * 2 + e;
                float z = ssum[col] + ssum[128 + col] + ssum[256 + col] + ssum[384 + col];
                int gidx = ((blockIdx.y * HB + n) * LL) + kc0 + col;
                g_pmax[gidx] = Mcol[nt][e];
                g_psum[gidx] = z;
            }
    }
}

// ---------------------------------------------------------------------------
// K3: combine 4 q-block partials -> column M and 1/Z. grid 256, block 256.
// ---------------------------------------------------------------------------
__global__ __launch_bounds__(256) void k_colstats() {
    int idx = blockIdx.x * 256 + threadIdx.x;
    float m0 = g_pmax[idx];
    float m1 = g_pmax[65536 + idx];
    float m2 = g_pmax[131072 + idx];
    float m3 = g_pmax[196608 + idx];
    float M = fmaxf(fmaxf(m0, m1), fmaxf(m2, m3));
    float Z = g_psum[idx] * __expf(m0 - M)
            + g_psum[65536 + idx] * __expf(m1 - M)
            + g_psum[131072 + idx] * __expf(m2 - M)
            + g_psum[196608 + idx] * __expf(m3 - M);
    g_M[idx] = M;
    g_inv[idx] = 1.0f / Z;
}

// ---------------------------------------------------------------------------
// K4: AV with fused softmax apply on A; writes ATT hi/lo planes.
// grid (1, 4, 128), block 256.
// ---------------------------------------------------------------------------
__global__ __launch_bounds__(256) void k_av() {
    extern __shared__ char sm[];
    uint32_t smb = smem_u32(sm);
    int tid = threadIdx.x, wid = tid >> 5, lane = tid & 31;
    int wm = wid & 3, wn = wid >> 2, g = lane >> 2, t = lane & 3;
    int n = blockIdx.z;
    int q0 = blockIdx.y * 128;

    float acc[2][8][4] = {};
    gemm_av(sm, smb, g_S + (n * LL + q0) * LL,
            g_Vh + n * (DD * LL), g_Vl + n * (DD * LL),
            LL, LL, 16, tid, wm, wn, g, t,
            g_M + n * LL, g_inv + n * LL, acc);

#pragma unroll
    for (int mt = 0; mt < 2; ++mt) {
#pragma unroll
        for (int nt = 0; nt < 8; ++nt) {
            int col = wn * 64 + nt * 8 + t * 2;
#pragma unroll
            for (int half = 0; half < 2; ++half) {
                int q = q0 + wm * 32 + mt * 16 + g + half * 8;
                int idx = (n * LL + q) * DD + col;
                uint32_t hh, ll;
                split_bf16(acc[mt][nt][half * 2], acc[mt][nt][half * 2 + 1], hh, ll);
                *(uint32_t*)&g_Ah[idx] = hh;
                *(uint32_t*)&g_Al[idx] = ll;
            }
        }
    }
}

// ---------------------------------------------------------------------------
// K5: output projection from ATT/Wo planes. grid (1, 64), block 256.
// ---------------------------------------------------------------------------
__global__ __launch_bounds__(256) void k_out(const float* __restrict__ bo,
                                             float* __restrict__ out) {
    extern __shared__ char sm[];
    uint32_t smb = smem_u32(sm);
    int tid = threadIdx.x, wid = tid >> 5, lane = tid & 31;
    int wm = wid & 3, wn = wid >> 2, g = lane >> 2, t = lane & 3;
    int m0 = blockIdx.y * 128;

    float acc[2][8][4] = {};
    gemm_pre(sm, smb, g_Ah + m0 * HD, g_Al + m0 * HD, g_Woh, g_Wol,
             HD, HD, 32, tid, wm, wn, g, t, acc);

#pragma unroll
    for (int mt = 0; mt < 2; ++mt) {
#pragma unroll
        for (int nt = 0; nt < 8; ++nt) {
            int col = wn * 64 + nt * 8 + t * 2;
            float b0 = bo[col], b1 = bo[col + 1];
#pragma unroll
            for (int half = 0; half < 2; ++half) {
                int m = m0 + wm * 32 + mt * 16 + g + half * 8;
                *(float2*)(out + m * DD + col) =
                    make_float2(acc[mt][nt][half * 2] + b0,
                                acc[mt][nt][half * 2 + 1] + b1);
            }
        }
    }
}

// ---------------------------------------------------------------------------
extern "C" void kernel_launch(void* const* d_in, const int* in_sizes, int n_in,
                              void* d_out, int out_size) {
    const float* x  = (const float*)d_in[0];
    const float* Wq = (const float*)d_in[1];
    const float* bq = (const float*)d_in[2];
    const float* Wk = (const float*)d_in[3];
    const float* bk = (const float*)d_in[4];
    const float* Wv = (const float*)d_in[5];
    const float* bv = (const float*)d_in[6];
    const float* Wo = (const float*)d_in[7];
    const float* bo = (const float*)d_in[8];
    const int*   mask = (const int*)d_in[9];
    float* out = (float*)d_out;

    cudaFuncSetAttribute(k_qkv,    cudaFuncAttributeMaxDynamicSharedMemorySize, SMEM_BYTES);
    cudaFuncSetAttribute(k_scores, cudaFuncAttributeMaxDynamicSharedMemorySize, SMEM_BYTES);
    cudaFuncSetAttribute(k_av,     cudaFuncAttributeMaxDynamicSharedMemorySize, SMEM_BYTES);
    cudaFuncSetAttribute(k_out,    cudaFuncAttributeMaxDynamicSharedMemorySize, SMEM_BYTES);

    // Device-symbol addresses for convert targets.
    uint16_t *xh, *xl, *wh, *wl, *woh, *wol;
    cudaGetSymbolAddress((void**)&xh,  g_xh);
    cudaGetSymbolAddress((void**)&xl,  g_xl);
    cudaGetSymbolAddress((void**)&wh,  g_Wh);
    cudaGetSymbolAddress((void**)&wl,  g_Wl);
    cudaGetSymbolAddress((void**)&woh, g_Woh);
    cudaGetSymbolAddress((void**)&wol, g_Wol);

    k_convert<<<(MM * DD / 2 + 255) / 256, 256>>>(x,  xh, xl, MM * DD / 2);
    k_convert<<<(HD * DD / 2 + 255) / 256, 256>>>(Wq, wh,              wl,              HD * DD / 2);
    k_convert<<<(HD * DD / 2 + 255) / 256, 256>>>(Wk, wh + HD * DD,     wl + HD * DD,     HD * DD / 2);
    k_convert<<<(DD * HD / 2 + 255) / 256, 256>>>(Wv, wh + 2 * HD * DD, wl + 2 * HD * DD, HD * DD / 2);
    k_convert<<<(DD * HD / 2 + 255) / 256, 256>>>(Wo, woh, wol, DD * HD / 2);

    k_qkv<<<dim3(8, 64, 3), 256, SMEM_BYTES>>>(bq, bk, bv);
    k_scores<<<dim3(4, 4, 128), 256, SMEM_BYTES>>>(mask);
    k_colstats<<<256, 256>>>();
    k_av<<<dim3(1, 4, 128), 256, SMEM_BYTES>>>();
    k_out<<<dim3(1, 64), 256, SMEM_BYTES>>>(bo, out);
}